// round 1
// baseline (speedup 1.0000x reference)
#include <cuda_runtime.h>
#include <cuda_bf16.h>

// Fused single-head causal attention, one CTA per batch element.
// x:[B,64,48] @ Wq/Wk/Wv:[48,48] -> q,k,v; wei = softmax(mask(q k^T / sqrt(48))); out = wei @ v.
// All fp32. Shared-memory resident per CTA; 256 threads; register-tiled GEMM phases.

#define T_DIM 64
#define C_DIM 48
#define H_DIM 48
#define XS 49   // padded row stride for x,q,k,v tiles (4*49 mod 32 = 4 -> distinct banks across t-tiles)
#define WS 68   // padded row stride for wei (4*68 mod 32 = 16 -> distinct banks across t-tiles)

// smem layout (floats):
//   sW   : 3*48*48 = 6912
//   sX   : 64*XS   = 3136
//   sQ   : 64*XS
//   sK   : 64*XS
//   sV   : 64*XS
//   sWei : 64*WS   = 4352
// total = 6912 + 4*3136 + 4352 = 23808 floats = 95232 bytes
#define SMEM_FLOATS (6912 + 4 * (T_DIM * XS) + (T_DIM * WS))

__global__ __launch_bounds__(256) void head_attn_kernel(
    const float* __restrict__ x,
    const float* __restrict__ Wq,
    const float* __restrict__ Wk,
    const float* __restrict__ Wv,
    float* __restrict__ out)
{
    extern __shared__ float smem[];
    float* sW   = smem;                  // [3][48][48]
    float* sX   = sW + 3 * 2304;         // [64][XS]
    float* sQ   = sX + T_DIM * XS;
    float* sK   = sQ + T_DIM * XS;
    float* sV   = sK + T_DIM * XS;
    float* sWei = sV + T_DIM * XS;       // [64][WS]

    const int tid = threadIdx.x;
    const long long b = blockIdx.x;

    // ---- Load weights (float4, contiguous) ----
    {
        const float4* wsrc0 = (const float4*)Wq;
        const float4* wsrc1 = (const float4*)Wk;
        const float4* wsrc2 = (const float4*)Wv;
        #pragma unroll 1
        for (int i = tid; i < 3 * 576; i += 256) {
            int m = i / 576;
            int j = i - m * 576;
            const float4* s = (m == 0) ? wsrc0 : (m == 1) ? wsrc1 : wsrc2;
            ((float4*)(sW + m * 2304))[j] = s[j];
        }
    }
    // ---- Load x[b] into padded smem rows (scalar, coalesced) ----
    {
        const float* xsrc = x + b * (T_DIM * C_DIM);
        #pragma unroll 1
        for (int i = tid; i < T_DIM * C_DIM; i += 256) {
            int r = i / C_DIM;
            int c = i - r * C_DIM;
            sX[r * XS + c] = xsrc[i];
        }
    }
    __syncthreads();

    const int tTile = tid >> 4;       // 0..15
    const int lo    = tid & 15;       // 0..15
    const int t0 = tTile * 4;
    const int h0 = lo * 3;            // projection/output column group (3 cols)
    const int s0 = lo * 4;            // score column group (4 cols)

    // ---- Phase 1: Q,K,V projections. Each thread: 4 rows x 3 cols x 3 matrices ----
    {
        float acc[3][12];
        #pragma unroll
        for (int m = 0; m < 3; ++m)
            #pragma unroll
            for (int j = 0; j < 12; ++j) acc[m][j] = 0.0f;

        #pragma unroll 4
        for (int c = 0; c < C_DIM; ++c) {
            float xv[4];
            #pragma unroll
            for (int i = 0; i < 4; ++i) xv[i] = sX[(t0 + i) * XS + c];
            #pragma unroll
            for (int m = 0; m < 3; ++m) {
                #pragma unroll
                for (int j = 0; j < 3; ++j) {
                    float wv = sW[m * 2304 + c * 48 + h0 + j];
                    #pragma unroll
                    for (int i = 0; i < 4; ++i)
                        acc[m][i * 3 + j] += xv[i] * wv;
                }
            }
        }
        #pragma unroll
        for (int i = 0; i < 4; ++i) {
            #pragma unroll
            for (int j = 0; j < 3; ++j) {
                sQ[(t0 + i) * XS + h0 + j] = acc[0][i * 3 + j];
                sK[(t0 + i) * XS + h0 + j] = acc[1][i * 3 + j];
                sV[(t0 + i) * XS + h0 + j] = acc[2][i * 3 + j];
            }
        }
    }
    __syncthreads();

    // ---- Phase 2: scores = Q K^T * scale, causal-masked. 4x4 tile per thread ----
    {
        float sc[16];
        #pragma unroll
        for (int j = 0; j < 16; ++j) sc[j] = 0.0f;

        #pragma unroll 4
        for (int h = 0; h < H_DIM; ++h) {
            float qv[4], kv[4];
            #pragma unroll
            for (int i = 0; i < 4; ++i) qv[i] = sQ[(t0 + i) * XS + h];
            #pragma unroll
            for (int i = 0; i < 4; ++i) kv[i] = sK[(s0 + i) * XS + h];
            #pragma unroll
            for (int i = 0; i < 4; ++i)
                #pragma unroll
                for (int j = 0; j < 4; ++j)
                    sc[i * 4 + j] += qv[i] * kv[j];
        }
        const float scale = 0.144337567297406441f; // 1/sqrt(48)
        #pragma unroll
        for (int i = 0; i < 4; ++i) {
            #pragma unroll
            for (int j = 0; j < 4; ++j) {
                int t = t0 + i, s = s0 + j;
                sWei[t * WS + s] = (s <= t) ? sc[i * 4 + j] * scale : -1e30f;
            }
        }
    }
    __syncthreads();

    // ---- Phase 3: row softmax. 8 warps x 8 rows; 2 elements per lane ----
    {
        const int warp = tid >> 5;
        const int lane = tid & 31;
        #pragma unroll 1
        for (int r8 = 0; r8 < 8; ++r8) {
            int r = warp * 8 + r8;
            float v0 = sWei[r * WS + lane];
            float v1 = sWei[r * WS + lane + 32];
            float mx = fmaxf(v0, v1);
            #pragma unroll
            for (int off = 16; off > 0; off >>= 1)
                mx = fmaxf(mx, __shfl_xor_sync(0xffffffffu, mx, off));
            float p0 = __expf(v0 - mx);
            float p1 = __expf(v1 - mx);
            float sum = p0 + p1;
            #pragma unroll
            for (int off = 16; off > 0; off >>= 1)
                sum += __shfl_xor_sync(0xffffffffu, sum, off);
            float inv = __fdividef(1.0f, sum);
            sWei[r * WS + lane]      = p0 * inv;
            sWei[r * WS + lane + 32] = p1 * inv;
        }
    }
    __syncthreads();

    // ---- Phase 4: out = wei @ V. 4 rows x 3 cols per thread ----
    {
        float oacc[12];
        #pragma unroll
        for (int j = 0; j < 12; ++j) oacc[j] = 0.0f;

        #pragma unroll 4
        for (int s = 0; s < T_DIM; ++s) {
            float wv[4];
            #pragma unroll
            for (int i = 0; i < 4; ++i) wv[i] = sWei[(t0 + i) * WS + s];
            #pragma unroll
            for (int j = 0; j < 3; ++j) {
                float vv = sV[s * XS + h0 + j];
                #pragma unroll
                for (int i = 0; i < 4; ++i)
                    oacc[i * 3 + j] += wv[i] * vv;
            }
        }
        float* op = out + b * (T_DIM * C_DIM);
        #pragma unroll
        for (int i = 0; i < 4; ++i)
            #pragma unroll
            for (int j = 0; j < 3; ++j)
                op[(t0 + i) * C_DIM + h0 + j] = oacc[i * 3 + j];
    }
}

extern "C" void kernel_launch(void* const* d_in, const int* in_sizes, int n_in,
                              void* d_out, int out_size)
{
    const float* x  = (const float*)d_in[0];
    const float* Wq = (const float*)d_in[1];
    const float* Wk = (const float*)d_in[2];
    const float* Wv = (const float*)d_in[3];
    float* out = (float*)d_out;

    const int B = in_sizes[0] / (T_DIM * C_DIM);   // 16384
    const size_t shmem = SMEM_FLOATS * sizeof(float);  // 95232 B

    cudaFuncSetAttribute(head_attn_kernel,
                         cudaFuncAttributeMaxDynamicSharedMemorySize, (int)shmem);

    head_attn_kernel<<<B, 256, shmem>>>(x, Wq, Wk, Wv, out);
}